// round 13
// baseline (speedup 1.0000x reference)
#include <cuda_runtime.h>
#include <cstdint>

// Problem constants (fixed by the reference: N=64, T=2048, F=256)
#define CBS_N 64
#define CBS_T 2048
#define CBS_F 256
#define CBS_F4 (CBS_F / 4)     // 64 float4 per (n, t) row
#define THREADS_PER_ROW 16      // each thread: 4 float4, INTERLEAVED stride 16
#define ROWS_PER_BLOCK (256 / THREADS_PER_ROW)   // 16

// CONVERGED FINAL KERNEL (best measured: 24.096us ncu in R12).
// Falsification matrix over R4-R12 (kernel times all 24.1-25.2us, DRAM
// 51-54%, no pipe saturated):
//   MLP 4 vs 8                      : invariant
//   __stcs vs plain stores          : invariant
//   __ldcs vs __ldg vs default ld   : invariant
//   block 256 vs 512                : invariant
//   multi-wave vs persistent grid   : invariant
// => steady-state mixed read/write HBM ceiling. Writes (134MB) are
//    mandatory (output poisoned each run); reads (~35MB valid windows)
//    irreducible. Bench scatter 26.6-30.3us over identical kernel times
//    is environment noise (graph overhead + L2 write-drain tail).
// Config: 4 interleaved float4/thread (f = lane + 16k -> every LDG/STG
// warp-dense), plain loads/stores, fused chunk_lens write, grid(128,64).

__device__ __forceinline__ int imax_(int a, int b) { return a > b ? a : b; }
__device__ __forceinline__ int imin_(int a, int b) { return a < b ? a : b; }

// grid = (T/16, N) = (128, 64), block = 256.
__global__ void __launch_bounds__(256)
chunk_by_slices_kernel(const float4* __restrict__ x,
                       const int* __restrict__ slices,
                       const int* __restrict__ lens,
                       float4* __restrict__ out,
                       float* __restrict__ out_lens) {
    const int n = blockIdx.y;

    // Per-row parameters; uniform across the block -> L1 broadcast.
    const int s = slices[2 * n];
    const int e = slices[2 * n + 1];
    const int chunk_len = imax_(e - s, 0);
    const int left_pad  = (chunk_len == 0) ? 0 : imax_(-s, 0);
    const int start_    = imax_(s, 0);
    const int end_      = imin_(e, lens[n]);
    const int slice_len = imax_(end_ - start_, 0);

    // Fused chunk_lens write (float32-encoded): one thread per n.
    if (blockIdx.x == 0 && threadIdx.x == 0) {
        out_lens[n] = (float)chunk_len;
    }

    const int t  = blockIdx.x * ROWS_PER_BLOCK + (threadIdx.x >> 4);
    const int f0 = threadIdx.x & 15;   // interleaved: f0 + 16k, k = 0..3

    const bool valid = (t >= left_pad) && (t < left_pad + slice_len);

    int src = start_ + t - left_pad;
    src = imin_(imax_(src, 0), CBS_T - 1);

    float4 v0, v1, v2, v3;
    if (valid) {
        const float4* xr = &x[(n * CBS_T + src) * CBS_F4 + f0];
        v0 = xr[0];
        v1 = xr[16];
        v2 = xr[32];
        v3 = xr[48];
    } else {
        v0 = v1 = v2 = v3 = make_float4(0.f, 0.f, 0.f, 0.f);
    }

    float4* op = &out[(n * CBS_T + t) * CBS_F4 + f0];
    op[0]  = v0;
    op[16] = v1;
    op[32] = v2;
    op[48] = v3;
}

extern "C" void kernel_launch(void* const* d_in, const int* in_sizes, int n_in,
                              void* d_out, int out_size) {
    const float4* x      = (const float4*)d_in[0];
    const int*    slices = (const int*)d_in[1];
    const int*    lens   = (const int*)d_in[2];
    float4*       out    = (float4*)d_out;

    const long long chunks_elems = (long long)CBS_N * CBS_T * CBS_F;
    float* out_lens = ((float*)d_out) + chunks_elems;

    dim3 block(256);
    dim3 grid(CBS_T / ROWS_PER_BLOCK, CBS_N);  // (128, 64)
    chunk_by_slices_kernel<<<grid, block>>>(x, slices, lens, out, out_lens);
}

// round 14
// speedup vs baseline: 1.0515x; 1.0515x over previous
#include <cuda_runtime.h>
#include <cstdint>

// Problem constants (fixed by the reference: N=64, T=2048, F=256)
#define CBS_N 64
#define CBS_T 2048
#define CBS_F 256
#define CBS_F4 (CBS_F / 4)     // 64 float4 per (n, t) row
#define THREADS_PER_ROW 16      // each thread: 4 float4, INTERLEAVED stride 16
#define ROWS_PER_BLOCK (256 / THREADS_PER_ROW)   // 16

// KEY FINDING (R13 re-analysis): bench times split cleanly by STORE POLICY
// even though ncu kernel times are invariant —
//   __stcs  benches: 26.6, 27.4, 28.7, 27.1   (mean 27.5)
//   plain   benches: 29.2, 30.3, 29.2, 30.7   (mean 29.9)
// ncu runs --cache-control all (flushed), so it cannot see steady-state
// L2 dirty-line churn across graph replays; the bench can. Evict-first /
// non-allocating stores save ~2.4us/replay of dirty-eviction overhead on
// the 134MB output rewrite. This round: __stwt (write-through) — never
// dirty L2 at all. Fallback if worse: __stcs config (R10).

__device__ __forceinline__ int imax_(int a, int b) { return a > b ? a : b; }
__device__ __forceinline__ int imin_(int a, int b) { return a < b ? a : b; }

// grid = (T/16, N) = (128, 64), block = 256.
__global__ void __launch_bounds__(256)
chunk_by_slices_wt_kernel(const float4* __restrict__ x,
                          const int* __restrict__ slices,
                          const int* __restrict__ lens,
                          float4* __restrict__ out,
                          float* __restrict__ out_lens) {
    const int n = blockIdx.y;

    // Per-row parameters; uniform across the block -> L1 broadcast.
    const int s = slices[2 * n];
    const int e = slices[2 * n + 1];
    const int chunk_len = imax_(e - s, 0);
    const int left_pad  = (chunk_len == 0) ? 0 : imax_(-s, 0);
    const int start_    = imax_(s, 0);
    const int end_      = imin_(e, lens[n]);
    const int slice_len = imax_(end_ - start_, 0);

    // Fused chunk_lens write (float32-encoded): one thread per n.
    if (blockIdx.x == 0 && threadIdx.x == 0) {
        out_lens[n] = (float)chunk_len;
    }

    const int t  = blockIdx.x * ROWS_PER_BLOCK + (threadIdx.x >> 4);
    const int f0 = threadIdx.x & 15;   // interleaved: f0 + 16k, k = 0..3

    const bool valid = (t >= left_pad) && (t < left_pad + slice_len);

    int src = start_ + t - left_pad;
    src = imin_(imax_(src, 0), CBS_T - 1);

    float4 v0, v1, v2, v3;
    if (valid) {
        const float4* xr = &x[(n * CBS_T + src) * CBS_F4 + f0];
        v0 = __ldg(xr + 0);     // cacheable reads: valid x windows stay
        v1 = __ldg(xr + 16);    // L2-resident across graph replays
        v2 = __ldg(xr + 32);
        v3 = __ldg(xr + 48);
    } else {
        v0 = v1 = v2 = v3 = make_float4(0.f, 0.f, 0.f, 0.f);
    }

    // Write-through: output never re-read, never dirties L2 -> no
    // dirty-line eviction churn between graph replays.
    float4* op = &out[(n * CBS_T + t) * CBS_F4 + f0];
    __stwt(op + 0,  v0);
    __stwt(op + 16, v1);
    __stwt(op + 32, v2);
    __stwt(op + 48, v3);
}

extern "C" void kernel_launch(void* const* d_in, const int* in_sizes, int n_in,
                              void* d_out, int out_size) {
    const float4* x      = (const float4*)d_in[0];
    const int*    slices = (const int*)d_in[1];
    const int*    lens   = (const int*)d_in[2];
    float4*       out    = (float4*)d_out;

    const long long chunks_elems = (long long)CBS_N * CBS_T * CBS_F;
    float* out_lens = ((float*)d_out) + chunks_elems;

    dim3 block(256);
    dim3 grid(CBS_T / ROWS_PER_BLOCK, CBS_N);  // (128, 64)
    chunk_by_slices_wt_kernel<<<grid, block>>>(x, slices, lens, out, out_lens);
}

// round 15
// speedup vs baseline: 1.1216x; 1.0667x over previous
#include <cuda_runtime.h>
#include <cstdint>

// Problem constants (fixed by the reference: N=64, T=2048, F=256)
#define CBS_N 64
#define CBS_T 2048
#define CBS_F 256
#define CBS_F4 (CBS_F / 4)     // 64 float4 per (n, t) row
#define THREADS_PER_ROW 16      // each thread: 4 float4, INTERLEAVED stride 16
#define ROWS_PER_BLOCK (256 / THREADS_PER_ROW)   // 16

// FINAL KERNEL — the empirically best configuration family.
//
// Store-policy axis fully mapped over R4-R14 (bench times; ncu kernel time
// is invariant at 24.1-25.2us because --cache-control all flushes the L2
// steady state the bench actually runs in):
//   __stcs (evict-first):  26.6, 27.4, 28.7, 27.1   <- winner, zero overlap
//   plain  (writeback):    29.2, 30.3, 29.2, 30.7
//   __stwt (write-through): 29.2
// Mechanism: evict-first output lines self-drain from L2 continuously;
// writeback/WT accumulate 134MB of dirty/probing traffic that collides
// with the next graph replay's writes (~2.4us/replay penalty).
// All other axes falsified: MLP 4/8, read policy (ldg/ldcs/default),
// block 256/512, multi-wave vs persistent grid.
//
// Config: 4 interleaved float4/thread (f = lane + 16k -> every LDG/STG
// warp-dense), __ldg reads (valid x windows stay L2-resident across
// replays), __stcs stores, fused chunk_lens write, grid(128,64) x 256.

__device__ __forceinline__ int imax_(int a, int b) { return a > b ? a : b; }
__device__ __forceinline__ int imin_(int a, int b) { return a < b ? a : b; }

// grid = (T/16, N) = (128, 64), block = 256.
__global__ void __launch_bounds__(256)
chunk_by_slices_kernel(const float4* __restrict__ x,
                       const int* __restrict__ slices,
                       const int* __restrict__ lens,
                       float4* __restrict__ out,
                       float* __restrict__ out_lens) {
    const int n = blockIdx.y;

    // Per-row parameters; uniform across the block -> L1 broadcast.
    const int s = slices[2 * n];
    const int e = slices[2 * n + 1];
    const int chunk_len = imax_(e - s, 0);
    const int left_pad  = (chunk_len == 0) ? 0 : imax_(-s, 0);
    const int start_    = imax_(s, 0);
    const int end_      = imin_(e, lens[n]);
    const int slice_len = imax_(end_ - start_, 0);

    // Fused chunk_lens write (float32-encoded): one thread per n.
    if (blockIdx.x == 0 && threadIdx.x == 0) {
        out_lens[n] = (float)chunk_len;
    }

    const int t  = blockIdx.x * ROWS_PER_BLOCK + (threadIdx.x >> 4);
    const int f0 = threadIdx.x & 15;   // interleaved: f0 + 16k, k = 0..3

    const bool valid = (t >= left_pad) && (t < left_pad + slice_len);

    int src = start_ + t - left_pad;
    src = imin_(imax_(src, 0), CBS_T - 1);

    float4 v0, v1, v2, v3;
    if (valid) {
        const float4* xr = &x[(n * CBS_T + src) * CBS_F4 + f0];
        v0 = __ldg(xr + 0);
        v1 = __ldg(xr + 16);
        v2 = __ldg(xr + 32);
        v3 = __ldg(xr + 48);
    } else {
        v0 = v1 = v2 = v3 = make_float4(0.f, 0.f, 0.f, 0.f);
    }

    float4* op = &out[(n * CBS_T + t) * CBS_F4 + f0];
    __stcs(op + 0,  v0);
    __stcs(op + 16, v1);
    __stcs(op + 32, v2);
    __stcs(op + 48, v3);
}

extern "C" void kernel_launch(void* const* d_in, const int* in_sizes, int n_in,
                              void* d_out, int out_size) {
    const float4* x      = (const float4*)d_in[0];
    const int*    slices = (const int*)d_in[1];
    const int*    lens   = (const int*)d_in[2];
    float4*       out    = (float4*)d_out;

    const long long chunks_elems = (long long)CBS_N * CBS_T * CBS_F;
    float* out_lens = ((float*)d_out) + chunks_elems;

    dim3 block(256);
    dim3 grid(CBS_T / ROWS_PER_BLOCK, CBS_N);  // (128, 64)
    chunk_by_slices_kernel<<<grid, block>>>(x, slices, lens, out, out_lens);
}

// round 16
// speedup vs baseline: 1.2248x; 1.0920x over previous
#include <cuda_runtime.h>
#include <cstdint>

// Problem constants (fixed by the reference: N=64, T=2048, F=256)
#define CBS_N 64
#define CBS_T 2048
#define CBS_F 256
#define CBS_F4 (CBS_F / 4)   // 64 float4 per (n, t) row

// REPLICATION RUN: exact R4 configuration (1 float4/thread + __stcs),
// which holds the session-best bench (26.6us).
//
// Established findings:
//  - Store policy dominates bench steady state (ncu can't see it:
//    --cache-control all flushes L2 between passes):
//      __stcs: 26.6, 27.1, 27.4, 27.4, 28.7 | plain: 29.2-30.7 | stwt: 29.2
//  - Within the stcs family, the single 1-f4/thread draw (26.6) beat all
//    4-interleaved draws (27.1/27.4/27.4). Hypothesis: 4x more warps ->
//    finer-grained store interleave across LTS slices -> smoother
//    evict-first drain under replay steady state (issue cost hidden since
//    DRAM scheduling binds). This run tests replication.

__device__ __forceinline__ int imax_(int a, int b) { return a > b ? a : b; }
__device__ __forceinline__ int imin_(int a, int b) { return a < b ? a : b; }

// One float4 per thread. grid = (T*F4/256, N) = (512, 64), block = 256.
__global__ void __launch_bounds__(256)
chunk_by_slices_r4_kernel(const float4* __restrict__ x,
                          const int* __restrict__ slices,
                          const int* __restrict__ lens,
                          float4* __restrict__ out,
                          float* __restrict__ out_lens) {
    const int n = blockIdx.y;

    // Per-row parameters; uniform across the block -> L1 broadcast.
    const int s = slices[2 * n];
    const int e = slices[2 * n + 1];
    const int chunk_len = imax_(e - s, 0);
    const int left_pad  = (chunk_len == 0) ? 0 : imax_(-s, 0);
    const int start_    = imax_(s, 0);
    const int end_      = imin_(e, lens[n]);
    const int slice_len = imax_(end_ - start_, 0);

    // Fused chunk_lens write (float32-encoded): one thread per n.
    if (blockIdx.x == 0 && threadIdx.x == 0) {
        out_lens[n] = (float)chunk_len;
    }

    const int tid = blockIdx.x * blockDim.x + threadIdx.x;  // over T*F4
    const int t = tid >> 6;          // / CBS_F4
    const int f = tid & (CBS_F4 - 1);

    const bool valid = (t >= left_pad) && (t < left_pad + slice_len);

    int src = start_ + t - left_pad;
    src = imin_(imax_(src, 0), CBS_T - 1);

    float4 v;
    if (valid) {
        v = __ldg(&x[(n * CBS_T + src) * CBS_F4 + f]);
    } else {
        v = make_float4(0.f, 0.f, 0.f, 0.f);
    }
    __stcs(&out[(n * CBS_T + t) * CBS_F4 + f], v);
}

extern "C" void kernel_launch(void* const* d_in, const int* in_sizes, int n_in,
                              void* d_out, int out_size) {
    const float4* x      = (const float4*)d_in[0];
    const int*    slices = (const int*)d_in[1];
    const int*    lens   = (const int*)d_in[2];
    float4*       out    = (float4*)d_out;

    const long long chunks_elems = (long long)CBS_N * CBS_T * CBS_F;
    float* out_lens = ((float*)d_out) + chunks_elems;

    dim3 block(256);
    dim3 grid((CBS_T * CBS_F4) / 256, CBS_N);  // (512, 64)
    chunk_by_slices_r4_kernel<<<grid, block>>>(x, slices, lens, out, out_lens);
}